// round 2
// baseline (speedup 1.0000x reference)
#include <cuda_runtime.h>
#include <cuda_bf16.h>
#include <math.h>

#define Bb   4
#define Cc   128
#define DI   256
#define Nn   16
#define Rr   8
#define Kk   4
#define Hh   48
#define Ww   48
#define LL   2304
#define BL   9216

// ---------------- scratch (device globals) ----------------
__device__ float g_xn   [(size_t)BL * Cc];
__device__ float g_xz   [(size_t)BL * 2 * DI];
__device__ float g_xhw  [(size_t)Bb * DI * LL];
__device__ float g_xwh  [(size_t)Bb * DI * LL];
__device__ float g_delta[(size_t)Bb * Kk * DI * LL];
__device__ float g_Bm   [(size_t)Bb * Kk * Nn * LL];
__device__ float g_Cm   [(size_t)Bb * Kk * Nn * LL];
__device__ float g_ys   [(size_t)Bb * Kk * DI * LL];
__device__ float g_ycomb[(size_t)BL * DI];
__device__ float g_yact [(size_t)BL * DI];

__device__ __forceinline__ float ex2f(float x){
    float r; asm("ex2.approx.f32 %0, %1;" : "=f"(r) : "f"(x)); return r;
}
__device__ __forceinline__ float sigmf(float x){
    return 1.f / (1.f + __expf(-x));
}

// ================= K0: channel LayerNorm -> xn (B*L, C) =================
__global__ void k0_ln(const float* __restrict__ x,
                      const float* __restrict__ lg, const float* __restrict__ lb)
{
    int b = blockIdx.x / Hh;
    int h = blockIdx.x % Hh;
    __shared__ float s[Cc][Ww + 1];
    __shared__ float mu[Ww], rs[Ww];

    const float* xb = x + (size_t)b * Cc * LL + (size_t)h * Ww;
    for (int idx = threadIdx.x; idx < Cc * Ww; idx += 256) {
        int c = idx / Ww, w = idx % Ww;
        s[c][w] = xb[(size_t)c * LL + w];
    }
    __syncthreads();
    if (threadIdx.x < Ww) {
        int w = threadIdx.x;
        float sm = 0.f, sq = 0.f;
        #pragma unroll 8
        for (int c = 0; c < Cc; c++) { float v = s[c][w]; sm += v; sq += v * v; }
        float m = sm * (1.f / Cc);
        float var = sq * (1.f / Cc) - m * m;
        mu[w] = m; rs[w] = rsqrtf(var + 1e-5f);
    }
    __syncthreads();
    float* out = g_xn + ((size_t)(b * LL + h * Ww)) * Cc;
    for (int idx = threadIdx.x; idx < Ww * Cc; idx += 256) {
        int w = idx >> 7, c = idx & 127;
        out[idx] = (s[c][w] - mu[w]) * rs[w] * lg[c] + lb[c];
    }
}

// ================= K1: xz = xn @ in_proj_w^T  (9216 x 512 x 128) =================
__global__ void __launch_bounds__(256) k1_gemm(const float* __restrict__ Wp)
{
    __shared__ float As[16][64];
    __shared__ float Bs[16][64];
    int m0 = blockIdx.x * 64, n0 = blockIdx.y * 64;
    int tid = threadIdx.x;
    int tm = tid & 15, tn = tid >> 4;
    int lr = tid >> 2, lk = (tid & 3) * 4;
    float acc[4][4];
    #pragma unroll
    for (int i = 0; i < 4; i++)
        #pragma unroll
        for (int j = 0; j < 4; j++) acc[i][j] = 0.f;

    for (int k0 = 0; k0 < Cc; k0 += 16) {
        float4 a4 = *(const float4*)(g_xn + (size_t)(m0 + lr) * Cc + k0 + lk);
        float4 b4 = *(const float4*)(Wp   + (size_t)(n0 + lr) * Cc + k0 + lk);
        As[lk][lr] = a4.x; As[lk+1][lr] = a4.y; As[lk+2][lr] = a4.z; As[lk+3][lr] = a4.w;
        Bs[lk][lr] = b4.x; Bs[lk+1][lr] = b4.y; Bs[lk+2][lr] = b4.z; Bs[lk+3][lr] = b4.w;
        __syncthreads();
        #pragma unroll
        for (int kk = 0; kk < 16; kk++) {
            float4 av = *(const float4*)(&As[kk][tm << 2]);
            float4 bv = *(const float4*)(&Bs[kk][tn << 2]);
            acc[0][0] = fmaf(av.x, bv.x, acc[0][0]); acc[0][1] = fmaf(av.x, bv.y, acc[0][1]);
            acc[0][2] = fmaf(av.x, bv.z, acc[0][2]); acc[0][3] = fmaf(av.x, bv.w, acc[0][3]);
            acc[1][0] = fmaf(av.y, bv.x, acc[1][0]); acc[1][1] = fmaf(av.y, bv.y, acc[1][1]);
            acc[1][2] = fmaf(av.y, bv.z, acc[1][2]); acc[1][3] = fmaf(av.y, bv.w, acc[1][3]);
            acc[2][0] = fmaf(av.z, bv.x, acc[2][0]); acc[2][1] = fmaf(av.z, bv.y, acc[2][1]);
            acc[2][2] = fmaf(av.z, bv.z, acc[2][2]); acc[2][3] = fmaf(av.z, bv.w, acc[2][3]);
            acc[3][0] = fmaf(av.w, bv.x, acc[3][0]); acc[3][1] = fmaf(av.w, bv.y, acc[3][1]);
            acc[3][2] = fmaf(av.w, bv.z, acc[3][2]); acc[3][3] = fmaf(av.w, bv.w, acc[3][3]);
        }
        __syncthreads();
    }
    #pragma unroll
    for (int i = 0; i < 4; i++) {
        float4 st = make_float4(acc[i][0], acc[i][1], acc[i][2], acc[i][3]);
        *(float4*)(g_xz + (size_t)(m0 + (tm << 2) + i) * 512 + n0 + (tn << 2)) = st;
    }
}

// ================= K2: depthwise conv3x3 + bias + SiLU -> x_hw, x_wh =================
__global__ void k2_conv(const float* __restrict__ cw, const float* __restrict__ cb)
{
    int bi  = blockIdx.x;
    int dci = bi & 15;
    int hci = (bi >> 4) % 6;
    int b   = bi / 96;
    int d0  = dci * 16;
    int hc  = hci * 8;
    int tid = threadIdx.x;

    __shared__ float sbuf[10][Ww][17];
    __shared__ float wgt[16][9];
    __shared__ float bia[16];

    if (tid < 144) wgt[tid / 9][tid % 9] = cw[(size_t)(d0 + tid / 9) * 9 + tid % 9];
    if (tid >= 144 && tid < 160) bia[tid - 144] = cb[d0 + tid - 144];

    for (int idx = tid; idx < 10 * Ww * 16; idx += 256) {
        int d = idx & 15;
        int rest = idx >> 4;
        int w = rest % Ww;
        int hh = rest / Ww;
        int gh = hc - 1 + hh;
        float v = 0.f;
        if (gh >= 0 && gh < Hh)
            v = g_xz[((size_t)(b * LL + gh * Ww + w)) * 512 + d0 + d];
        sbuf[hh][w][d] = v;
    }
    __syncthreads();

    float outv[24];
    #pragma unroll
    for (int it = 0; it < 24; it++) {
        int idx = tid + it * 256;
        int d = idx / 384;
        int r = idx % 384;
        int h = r / Ww;
        int w = r % Ww;
        float sum = bia[d];
        #pragma unroll
        for (int i = 0; i < 3; i++) {
            #pragma unroll
            for (int j = 0; j < 3; j++) {
                int ww = w + j - 1;
                float xv = (ww >= 0 && ww < Ww) ? sbuf[h + i][ww][d] : 0.f;
                sum = fmaf(wgt[d][i * 3 + j], xv, sum);
            }
        }
        outv[it] = sum * sigmf(sum);
    }
    __syncthreads();
    // write x_hw directly + stash for x_wh
    #pragma unroll
    for (int it = 0; it < 24; it++) {
        int idx = tid + it * 256;
        int d = idx / 384; int r = idx % 384; int h = r / Ww; int w = r % Ww;
        g_xhw[((size_t)(b * DI + d0 + d)) * LL + (hc + h) * Ww + w] = outv[it];
        sbuf[h][w][d] = outv[it];
    }
    __syncthreads();
    for (int it = 0; it < 24; it++) {
        int idx = tid + it * 256;
        int d = idx / 384; int r = idx % 384; int w = r >> 3; int h = r & 7;
        g_xwh[((size_t)(b * DI + d0 + d)) * LL + w * Hh + hc + h] = sbuf[h][w][d];
    }
}

// ================= K3: x_proj + dt projection + softplus =================
// per (b,k,l-tile 128): x_dbl = xs @ xpw^T ; writes Bm,Cm,delta (all in scan order)
__global__ void __launch_bounds__(256) k3_xproj(const float* __restrict__ xpw,
                         const float* __restrict__ dtwg,
                         const float* __restrict__ dtbg)
{
    int lt = blockIdx.x % 18;
    int bk = blockIdx.x / 18;
    int k  = bk & 3;
    int b  = bk >> 2;
    int l0 = lt * 128;
    int tid = threadIdx.x;
    int ll = tid & 127, q = tid >> 7;

    __shared__ float xd[40][128];
    __shared__ float us[32 * 128];
    __shared__ float wp2[32][2][20];

    const float* usrc = (((k & 1) == 0) ? g_xhw : g_xwh) + (size_t)b * DI * LL;
    bool rev = (k >= 2);

    float acc[20];
    #pragma unroll
    for (int j = 0; j < 20; j++) acc[j] = 0.f;

    for (int dc = 0; dc < DI; dc += 32) {
        for (int idx = tid; idx < 32 * 128; idx += 256) {
            int dd = idx >> 7, li = idx & 127;
            int gl = rev ? (LL - 1 - (l0 + li)) : (l0 + li);
            us[idx] = usrc[(size_t)(dc + dd) * LL + gl];
        }
        for (int idx = tid; idx < 1280; idx += 256) {
            int dd = idx / 40, c = idx % 40;
            wp2[dd][c & 1][c >> 1] = xpw[(size_t)(k * 40 + c) * DI + dc + dd];
        }
        __syncthreads();
        #pragma unroll 4
        for (int dd = 0; dd < 32; dd++) {
            float u = us[dd * 128 + ll];
            const float* w = &wp2[dd][q][0];
            #pragma unroll
            for (int j = 0; j < 20; j++) acc[j] = fmaf(w[j], u, acc[j]);
        }
        __syncthreads();
    }
    #pragma unroll
    for (int j = 0; j < 20; j++) xd[q + 2 * j][ll] = acc[j];
    __syncthreads();

    for (int idx = tid; idx < Nn * 128; idx += 256) {
        int nn = idx >> 7, li = idx & 127;
        g_Bm[((size_t)bk * Nn + nn) * LL + l0 + li] = xd[Rr + nn][li];
        g_Cm[((size_t)bk * Nn + nn) * LL + l0 + li] = xd[Rr + Nn + nn][li];
    }
    for (int idx = tid; idx < DI * Rr; idx += 256)
        us[idx] = dtwg[(size_t)k * DI * Rr + idx];
    float dtr[8];
    #pragma unroll
    for (int r = 0; r < 8; r++) dtr[r] = xd[r][ll];
    __syncthreads();

    const float* dtb = dtbg + k * DI;
    #pragma unroll 2
    for (int dd = 0; dd < 128; dd++) {
        int d = (q << 7) + dd;
        float4 w0 = *(const float4*)&us[d * 8];
        float4 w1 = *(const float4*)&us[d * 8 + 4];
        float a = dtb[d];
        a = fmaf(w0.x, dtr[0], a); a = fmaf(w0.y, dtr[1], a);
        a = fmaf(w0.z, dtr[2], a); a = fmaf(w0.w, dtr[3], a);
        a = fmaf(w1.x, dtr[4], a); a = fmaf(w1.y, dtr[5], a);
        a = fmaf(w1.z, dtr[6], a); a = fmaf(w1.w, dtr[7], a);
        float sp = fmaxf(a, 0.f) + __logf(1.f + __expf(-fabsf(a)));
        g_delta[((size_t)bk * DI + d) * LL + l0 + ll] = sp;
    }
}

// ================= K4: selective scan (lane-per-(d,n)) =================
__global__ void __launch_bounds__(128) k4_scan(const float* __restrict__ A_logs,
                                               const float* __restrict__ Ds)
{
    int dg = blockIdx.x & 31;       // d-group of 8
    int bk = blockIdx.x >> 5;       // 0..15
    int k  = bk & 3;
    int b  = bk >> 2;
    int lane = threadIdx.x & 31;
    int warp = threadIdx.x >> 5;    // 0..3
    int half = lane >> 4;
    int n    = lane & 15;
    int d    = dg * 8 + warp * 2 + half;

    float aa = -expf(A_logs[((size_t)(k * DI + d)) * Nn + n]) * 1.44269504088896f;
    float Dv = Ds[k * DI + d];

    const float* dp = g_delta + ((size_t)bk * DI + d) * LL;
    const float* up = ((((k & 1) == 0) ? g_xhw : g_xwh)) + ((size_t)(b * DI + d)) * LL;
    const float* Bp = g_Bm + ((size_t)bk * Nn + n) * LL;
    const float* Cp = g_Cm + ((size_t)bk * Nn + n) * LL;
    bool rev = (k >= 2);

    __shared__ float yb[4][2][64];
    float h = 0.f;

    for (int t0 = 0; t0 < LL; t0 += 64) {
        #pragma unroll 4
        for (int tt = 0; tt < 64; tt += 4) {
            int t = t0 + tt;
            float4 dl = *(const float4*)(dp + t);
            float4 uu;
            if (!rev) uu = *(const float4*)(up + t);
            else { float4 tp = *(const float4*)(up + (LL - 4 - t));
                   uu.x = tp.w; uu.y = tp.z; uu.z = tp.y; uu.w = tp.x; }
            float4 Bv = *(const float4*)(Bp + t);
            float4 Cv = *(const float4*)(Cp + t);

            #define SSTEP(DL,UU,BB,CCv,J)  {                                  \
                float dA = ex2f((DL) * aa);                                   \
                float du = (DL) * (UU);                                       \
                h = fmaf(h, dA, du * (BB));                                   \
                float p = h * (CCv);                                          \
                p += __shfl_xor_sync(0xffffffffu, p, 8);                      \
                p += __shfl_xor_sync(0xffffffffu, p, 4);                      \
                p += __shfl_xor_sync(0xffffffffu, p, 2);                      \
                p += __shfl_xor_sync(0xffffffffu, p, 1);                      \
                if (n == 0) yb[warp][half][tt + (J)] = fmaf(Dv, (UU), p); }

            SSTEP(dl.x, uu.x, Bv.x, Cv.x, 0)
            SSTEP(dl.y, uu.y, Bv.y, Cv.y, 1)
            SSTEP(dl.z, uu.z, Bv.z, Cv.z, 2)
            SSTEP(dl.w, uu.w, Bv.w, Cv.w, 3)
            #undef SSTEP
        }
        __syncwarp();
        int idx  = lane * 4;
        int hsel = idx >> 6;
        int off  = idx & 63;
        float4 v = *(float4*)&yb[warp][hsel][off];
        *(float4*)(g_ys + ((size_t)bk * DI + dg * 8 + warp * 2 + hsel) * LL + t0 + off) = v;
        __syncwarp();
    }
}

// ================= K5: combine the four direction outputs =================
__global__ void k5_combine()
{
    int hc = blockIdx.x % 6;
    int dc = (blockIdx.x / 6) & 15;
    int b  = blockIdx.x / 96;
    int d0 = dc * 16, h0 = hc * 8;
    __shared__ float s[16][392];
    int tid = threadIdx.x;
    const float* y0 = g_ys + ((size_t)(b * 4 + 0) * DI + d0) * LL;
    const float* y1 = g_ys + ((size_t)(b * 4 + 1) * DI + d0) * LL;
    const float* y2 = g_ys + ((size_t)(b * 4 + 2) * DI + d0) * LL;
    const float* y3 = g_ys + ((size_t)(b * 4 + 3) * DI + d0) * LL;
    int base = h0 * Ww;

    for (int idx = tid; idx < 16 * 384; idx += 256) {
        int d = idx / 384, p = idx % 384;
        int l = base + p;
        s[d][p] = y0[(size_t)d * LL + l] + y2[(size_t)d * LL + (LL - 1 - l)];
    }
    __syncthreads();
    for (int idx = tid; idx < 16 * 384; idx += 256) {
        int d = idx / 384, p = idx % 384;
        int w = p >> 3, hh = p & 7;
        int t1 = w * Hh + h0 + hh;
        float v = y1[(size_t)d * LL + t1] + y3[(size_t)d * LL + (LL - 1 - t1)];
        s[d][hh * Ww + w] += v;
    }
    __syncthreads();
    for (int idx = tid; idx < 384 * 16; idx += 256) {
        int p = idx >> 4, d = idx & 15;
        g_ycomb[((size_t)(b * LL + base + p)) * DI + d0 + d] = s[d][p];
    }
}

// ================= K6: LayerNorm(DI) + SiLU(z) gate =================
__global__ void k6_lngate(const float* __restrict__ og, const float* __restrict__ ob)
{
    int m = blockIdx.x;
    int tid = threadIdx.x;
    float v = g_ycomb[(size_t)m * DI + tid];
    float sm = v, sq = v * v;
    #pragma unroll
    for (int o = 16; o; o >>= 1) {
        sm += __shfl_xor_sync(0xffffffffu, sm, o);
        sq += __shfl_xor_sync(0xffffffffu, sq, o);
    }
    __shared__ float rs1[8], rs2[8];
    int w = tid >> 5, ln = tid & 31;
    if (ln == 0) { rs1[w] = sm; rs2[w] = sq; }
    __syncthreads();
    float ts = 0.f, tq = 0.f;
    #pragma unroll
    for (int i = 0; i < 8; i++) { ts += rs1[i]; tq += rs2[i]; }
    float mean = ts * (1.f / DI);
    float var  = tq * (1.f / DI) - mean * mean;
    float rstd = rsqrtf(var + 1e-5f);
    float zv = g_xz[(size_t)m * 512 + DI + tid];
    float gate = zv * sigmf(zv);
    g_yact[(size_t)m * DI + tid] = ((v - mean) * rstd * og[tid] + ob[tid]) * gate;
}

// ================= K7: out = x + (yact @ out_proj_w^T) transposed to (B,C,L) =================
__global__ void __launch_bounds__(256) k7_out(const float* __restrict__ Wout,
                                              const float* __restrict__ x,
                                              float* __restrict__ out)
{
    int b  = blockIdx.z;
    int c0 = blockIdx.y * 64;
    int l0 = blockIdx.x * 64;
    __shared__ float As[16][64];   // [k][c]
    __shared__ float Bs[16][64];   // [k][l]
    int tid = threadIdx.x;
    int tc = tid & 15, tl = tid >> 4;
    int lr = tid >> 2, lk = (tid & 3) * 4;
    float acc[4][4];
    #pragma unroll
    for (int i = 0; i < 4; i++)
        #pragma unroll
        for (int j = 0; j < 4; j++) acc[i][j] = 0.f;

    const float* Y = g_yact + (size_t)b * LL * DI;
    for (int k0 = 0; k0 < DI; k0 += 16) {
        float4 a4 = *(const float4*)(Wout + (size_t)(c0 + lr) * DI + k0 + lk);
        float4 b4 = *(const float4*)(Y    + (size_t)(l0 + lr) * DI + k0 + lk);
        As[lk][lr] = a4.x; As[lk+1][lr] = a4.y; As[lk+2][lr] = a4.z; As[lk+3][lr] = a4.w;
        Bs[lk][lr] = b4.x; Bs[lk+1][lr] = b4.y; Bs[lk+2][lr] = b4.z; Bs[lk+3][lr] = b4.w;
        __syncthreads();
        #pragma unroll
        for (int kk = 0; kk < 16; kk++) {
            float4 av = *(const float4*)(&As[kk][tc << 2]);
            float4 bv = *(const float4*)(&Bs[kk][tl << 2]);
            acc[0][0] = fmaf(av.x, bv.x, acc[0][0]); acc[0][1] = fmaf(av.x, bv.y, acc[0][1]);
            acc[0][2] = fmaf(av.x, bv.z, acc[0][2]); acc[0][3] = fmaf(av.x, bv.w, acc[0][3]);
            acc[1][0] = fmaf(av.y, bv.x, acc[1][0]); acc[1][1] = fmaf(av.y, bv.y, acc[1][1]);
            acc[1][2] = fmaf(av.y, bv.z, acc[1][2]); acc[1][3] = fmaf(av.y, bv.w, acc[1][3]);
            acc[2][0] = fmaf(av.z, bv.x, acc[2][0]); acc[2][1] = fmaf(av.z, bv.y, acc[2][1]);
            acc[2][2] = fmaf(av.z, bv.z, acc[2][2]); acc[2][3] = fmaf(av.z, bv.w, acc[2][3]);
            acc[3][0] = fmaf(av.w, bv.x, acc[3][0]); acc[3][1] = fmaf(av.w, bv.y, acc[3][1]);
            acc[3][2] = fmaf(av.w, bv.z, acc[3][2]); acc[3][3] = fmaf(av.w, bv.w, acc[3][3]);
        }
        __syncthreads();
    }
    #pragma unroll
    for (int i = 0; i < 4; i++) {
        int c = c0 + (tc << 2) + i;
        size_t off = ((size_t)b * Cc + c) * LL + l0 + (tl << 2);
        float4 xv = *(const float4*)(x + off);
        float4 st = make_float4(acc[i][0] + xv.x, acc[i][1] + xv.y,
                                acc[i][2] + xv.z, acc[i][3] + xv.w);
        *(float4*)(out + off) = st;
    }
}

extern "C" void kernel_launch(void* const* d_in, const int* in_sizes, int n_in,
                              void* d_out, int out_size)
{
    const float* x          = (const float*)d_in[0];
    const float* ln1_g      = (const float*)d_in[1];
    const float* ln1_b      = (const float*)d_in[2];
    const float* in_proj_w  = (const float*)d_in[3];
    const float* conv_w     = (const float*)d_in[4];
    const float* conv_b     = (const float*)d_in[5];
    const float* x_proj_w   = (const float*)d_in[6];
    const float* dt_w       = (const float*)d_in[7];
    const float* dt_b       = (const float*)d_in[8];
    const float* A_logs     = (const float*)d_in[9];
    const float* Ds         = (const float*)d_in[10];
    const float* outn_g     = (const float*)d_in[11];
    const float* outn_b     = (const float*)d_in[12];
    const float* out_proj_w = (const float*)d_in[13];
    float* out = (float*)d_out;

    k0_ln<<<Bb * Hh, 256>>>(x, ln1_g, ln1_b);
    { dim3 g(BL / 64, 512 / 64); k1_gemm<<<g, 256>>>(in_proj_w); }
    k2_conv<<<Bb * 6 * 16, 256>>>(conv_w, conv_b);
    k3_xproj<<<Bb * Kk * 18, 256>>>(x_proj_w, dt_w, dt_b);
    k4_scan<<<32 * 16, 128>>>(A_logs, Ds);
    k5_combine<<<Bb * 16 * 6, 256>>>();
    k6_lngate<<<BL, 256>>>(outn_g, outn_b);
    { dim3 g(LL / 64, Cc / 64, Bb); k7_out<<<g, 256>>>(out_proj_w, x, out); }
}

// round 4
// speedup vs baseline: 1.1054x; 1.1054x over previous
#include <cuda_runtime.h>
#include <cuda_bf16.h>
#include <math.h>

#define Bb   4
#define Cc   128
#define DI   256
#define Nn   16
#define Rr   8
#define Kk   4
#define Hh   48
#define Ww   48
#define LL   2304
#define BL   9216

// ---------------- scratch (device globals) ----------------
__device__ float g_xn   [(size_t)BL * Cc];
__device__ float g_xz   [(size_t)BL * 2 * DI];
__device__ float g_xhw  [(size_t)Bb * DI * LL];
__device__ float g_xwh  [(size_t)Bb * DI * LL];
__device__ float g_delta[(size_t)Bb * Kk * DI * LL];
__device__ float g_Bm   [(size_t)Bb * Kk * Nn * LL];
__device__ float g_Cm   [(size_t)Bb * Kk * Nn * LL];
__device__ float g_ys   [(size_t)Bb * Kk * DI * LL];
__device__ float g_ycomb[(size_t)BL * DI];
__device__ float g_yact [(size_t)BL * DI];

__device__ __forceinline__ float ex2f(float x){
    float r; asm("ex2.approx.f32 %0, %1;" : "=f"(r) : "f"(x)); return r;
}
__device__ __forceinline__ float sigmf(float x){
    return 1.f / (1.f + __expf(-x));
}

// ================= K0: channel LayerNorm -> xn (B*L, C) =================
__global__ void k0_ln(const float* __restrict__ x,
                      const float* __restrict__ lg, const float* __restrict__ lb)
{
    int b = blockIdx.x / Hh;
    int h = blockIdx.x % Hh;
    __shared__ float s[Cc][Ww + 1];
    __shared__ float mu[Ww], rs[Ww];

    const float* xb = x + (size_t)b * Cc * LL + (size_t)h * Ww;
    for (int idx = threadIdx.x; idx < Cc * Ww; idx += 256) {
        int c = idx / Ww, w = idx % Ww;
        s[c][w] = xb[(size_t)c * LL + w];
    }
    __syncthreads();
    if (threadIdx.x < Ww) {
        int w = threadIdx.x;
        float sm = 0.f, sq = 0.f;
        #pragma unroll 8
        for (int c = 0; c < Cc; c++) { float v = s[c][w]; sm += v; sq += v * v; }
        float m = sm * (1.f / Cc);
        float var = sq * (1.f / Cc) - m * m;
        mu[w] = m; rs[w] = rsqrtf(var + 1e-5f);
    }
    __syncthreads();
    float* out = g_xn + ((size_t)(b * LL + h * Ww)) * Cc;
    for (int idx = threadIdx.x; idx < Ww * Cc; idx += 256) {
        int w = idx >> 7, c = idx & 127;
        out[idx] = (s[c][w] - mu[w]) * rs[w] * lg[c] + lb[c];
    }
}

// ================= K1: xz = xn @ in_proj_w^T  (9216 x 512 x 128), 128x128 tile, 8x8 micro =================
__global__ void __launch_bounds__(256) k1_gemm(const float* __restrict__ Wp)
{
    __shared__ float As[16][128];
    __shared__ float Bs[16][128];
    int m0 = blockIdx.x * 128, n0 = blockIdx.y * 128;
    int tid = threadIdx.x;
    int tm = tid & 15, tn = tid >> 4;
    int row = tid >> 1, kq = (tid & 1) * 8;
    float acc[8][8];
    #pragma unroll
    for (int i = 0; i < 8; i++)
        #pragma unroll
        for (int j = 0; j < 8; j++) acc[i][j] = 0.f;

    for (int k0 = 0; k0 < Cc; k0 += 16) {
        float4 a0 = *(const float4*)(g_xn + (size_t)(m0 + row) * Cc + k0 + kq);
        float4 a1 = *(const float4*)(g_xn + (size_t)(m0 + row) * Cc + k0 + kq + 4);
        float4 b0 = *(const float4*)(Wp   + (size_t)(n0 + row) * Cc + k0 + kq);
        float4 b1 = *(const float4*)(Wp   + (size_t)(n0 + row) * Cc + k0 + kq + 4);
        __syncthreads();
        As[kq+0][row]=a0.x; As[kq+1][row]=a0.y; As[kq+2][row]=a0.z; As[kq+3][row]=a0.w;
        As[kq+4][row]=a1.x; As[kq+5][row]=a1.y; As[kq+6][row]=a1.z; As[kq+7][row]=a1.w;
        Bs[kq+0][row]=b0.x; Bs[kq+1][row]=b0.y; Bs[kq+2][row]=b0.z; Bs[kq+3][row]=b0.w;
        Bs[kq+4][row]=b1.x; Bs[kq+5][row]=b1.y; Bs[kq+6][row]=b1.z; Bs[kq+7][row]=b1.w;
        __syncthreads();
        #pragma unroll
        for (int kk = 0; kk < 16; kk++) {
            float4 av0 = *(const float4*)&As[kk][tm << 3];
            float4 av1 = *(const float4*)&As[kk][(tm << 3) + 4];
            float4 bv0 = *(const float4*)&Bs[kk][tn << 3];
            float4 bv1 = *(const float4*)&Bs[kk][(tn << 3) + 4];
            float am[8] = {av0.x,av0.y,av0.z,av0.w,av1.x,av1.y,av1.z,av1.w};
            float bn[8] = {bv0.x,bv0.y,bv0.z,bv0.w,bv1.x,bv1.y,bv1.z,bv1.w};
            #pragma unroll
            for (int i = 0; i < 8; i++)
                #pragma unroll
                for (int j = 0; j < 8; j++)
                    acc[i][j] = fmaf(am[i], bn[j], acc[i][j]);
        }
    }
    #pragma unroll
    for (int i = 0; i < 8; i++) {
        float* o = g_xz + (size_t)(m0 + (tm << 3) + i) * 512 + n0 + (tn << 3);
        *(float4*)o       = make_float4(acc[i][0], acc[i][1], acc[i][2], acc[i][3]);
        *(float4*)(o + 4) = make_float4(acc[i][4], acc[i][5], acc[i][6], acc[i][7]);
    }
}

// ================= K2: depthwise conv3x3 + bias + SiLU -> x_hw, x_wh =================
__global__ void k2_conv(const float* __restrict__ cw, const float* __restrict__ cb)
{
    int bi  = blockIdx.x;
    int dci = bi & 15;
    int hci = (bi >> 4) % 6;
    int b   = bi / 96;
    int d0  = dci * 16;
    int hc  = hci * 8;
    int tid = threadIdx.x;

    __shared__ float sbuf[10][Ww][17];
    __shared__ float wgt[16][9];
    __shared__ float bia[16];

    if (tid < 144) wgt[tid / 9][tid % 9] = cw[(size_t)(d0 + tid / 9) * 9 + tid % 9];
    if (tid >= 144 && tid < 160) bia[tid - 144] = cb[d0 + tid - 144];

    for (int idx = tid; idx < 10 * Ww * 16; idx += 256) {
        int d = idx & 15;
        int rest = idx >> 4;
        int w = rest % Ww;
        int hh = rest / Ww;
        int gh = hc - 1 + hh;
        float v = 0.f;
        if (gh >= 0 && gh < Hh)
            v = g_xz[((size_t)(b * LL + gh * Ww + w)) * 512 + d0 + d];
        sbuf[hh][w][d] = v;
    }
    __syncthreads();

    float outv[24];
    #pragma unroll
    for (int it = 0; it < 24; it++) {
        int idx = tid + it * 256;
        int d = idx / 384;
        int r = idx % 384;
        int h = r / Ww;
        int w = r % Ww;
        float sum = bia[d];
        #pragma unroll
        for (int i = 0; i < 3; i++) {
            #pragma unroll
            for (int j = 0; j < 3; j++) {
                int ww = w + j - 1;
                float xv = (ww >= 0 && ww < Ww) ? sbuf[h + i][ww][d] : 0.f;
                sum = fmaf(wgt[d][i * 3 + j], xv, sum);
            }
        }
        outv[it] = sum * sigmf(sum);
    }
    __syncthreads();
    #pragma unroll
    for (int it = 0; it < 24; it++) {
        int idx = tid + it * 256;
        int d = idx / 384; int r = idx % 384; int h = r / Ww; int w = r % Ww;
        g_xhw[((size_t)(b * DI + d0 + d)) * LL + (hc + h) * Ww + w] = outv[it];
        sbuf[h][w][d] = outv[it];
    }
    __syncthreads();
    for (int it = 0; it < 24; it++) {
        int idx = tid + it * 256;
        int d = idx / 384; int r = idx % 384; int w = r >> 3; int h = r & 7;
        g_xwh[((size_t)(b * DI + d0 + d)) * LL + w * Hh + hc + h] = sbuf[h][w][d];
    }
}

// ================= K3: x_proj + dt projection + softplus (direct LDG, no staging) =================
__global__ void __launch_bounds__(256) k3_xproj(const float* __restrict__ xpw,
                         const float* __restrict__ dtwg,
                         const float* __restrict__ dtbg)
{
    int lt = blockIdx.x % 18;
    int bk = blockIdx.x / 18;
    int k  = bk & 3;
    int b  = bk >> 2;
    int l0 = lt * 128;
    int tid = threadIdx.x;
    int ll = tid & 127, q = tid >> 7;

    __shared__ float xd[40][128];
    __shared__ float wp2[32][2][20];
    __shared__ float dtw[DI * Rr];

    const float* usrc = (((k & 1) == 0) ? g_xhw : g_xwh) + (size_t)b * DI * LL;
    bool rev = (k >= 2);
    int gl = rev ? (LL - 1 - (l0 + ll)) : (l0 + ll);

    for (int idx = tid; idx < DI * Rr; idx += 256)
        dtw[idx] = dtwg[(size_t)k * DI * Rr + idx];

    float acc[20];
    #pragma unroll
    for (int j = 0; j < 20; j++) acc[j] = 0.f;

    for (int dc = 0; dc < DI; dc += 32) {
        __syncthreads();
        for (int idx = tid; idx < 1280; idx += 256) {
            int c = idx >> 5, dd = idx & 31;
            wp2[dd][c & 1][c >> 1] = xpw[(size_t)(k * 40 + c) * DI + dc + dd];
        }
        __syncthreads();
        #pragma unroll
        for (int dd0 = 0; dd0 < 32; dd0 += 8) {
            float uv[8];
            #pragma unroll
            for (int i = 0; i < 8; i++)
                uv[i] = usrc[(size_t)(dc + dd0 + i) * LL + gl];
            #pragma unroll
            for (int i = 0; i < 8; i++) {
                const float* w = &wp2[dd0 + i][q][0];
                float u = uv[i];
                #pragma unroll
                for (int j = 0; j < 20; j++) acc[j] = fmaf(w[j], u, acc[j]);
            }
        }
    }
    __syncthreads();
    #pragma unroll
    for (int j = 0; j < 20; j++) xd[q + 2 * j][ll] = acc[j];
    __syncthreads();

    for (int idx = tid; idx < Nn * 128; idx += 256) {
        int nn = idx >> 7, li = idx & 127;
        g_Bm[((size_t)bk * Nn + nn) * LL + l0 + li] = xd[Rr + nn][li];
        g_Cm[((size_t)bk * Nn + nn) * LL + l0 + li] = xd[Rr + Nn + nn][li];
    }
    float dtr[8];
    #pragma unroll
    for (int r = 0; r < 8; r++) dtr[r] = xd[r][ll];

    const float* dtb = dtbg + k * DI;
    #pragma unroll 2
    for (int dd = 0; dd < 128; dd++) {
        int d = (q << 7) + dd;
        float4 w0 = *(const float4*)&dtw[d * 8];
        float4 w1 = *(const float4*)&dtw[d * 8 + 4];
        float a = dtb[d];
        a = fmaf(w0.x, dtr[0], a); a = fmaf(w0.y, dtr[1], a);
        a = fmaf(w0.z, dtr[2], a); a = fmaf(w0.w, dtr[3], a);
        a = fmaf(w1.x, dtr[4], a); a = fmaf(w1.y, dtr[5], a);
        a = fmaf(w1.z, dtr[6], a); a = fmaf(w1.w, dtr[7], a);
        float sp = fmaxf(a, 0.f) + __logf(1.f + __expf(-fabsf(a)));
        g_delta[((size_t)bk * DI + d) * LL + l0 + ll] = sp;
    }
}

// ================= K4: selective scan — prefetch + distributed butterfly reduce =================
__global__ void __launch_bounds__(128) k4_scan(const float* __restrict__ A_logs,
                                               const float* __restrict__ Ds)
{
    int dg = blockIdx.x & 31;
    int bk = blockIdx.x >> 5;
    int k  = bk & 3;
    int b  = bk >> 2;
    int lane = threadIdx.x & 31;
    int warp = threadIdx.x >> 5;
    int half = lane >> 4;
    int n    = lane & 15;
    int d    = dg * 8 + warp * 2 + half;

    float aa   = -expf(A_logs[((size_t)(k * DI + d)) * Nn + n]) * 1.44269504088896f;
    float Dv16 = Ds[k * DI + d] * 0.0625f;   // D/16: summed exactly over 16 lanes

    const float* dp = g_delta + ((size_t)bk * DI + d) * LL;
    const float* up = ((((k & 1) == 0) ? g_xhw : g_xwh)) + ((size_t)(b * DI + d)) * LL;
    const float* Bp = g_Bm + ((size_t)bk * Nn + n) * LL;
    const float* Cp = g_Cm + ((size_t)bk * Nn + n) * LL;
    const bool rev = (k >= 2);

    // lane -> which of the 8 chunk-steps this lane's reduced value belongs to
    int ln4 = lane & 15;
    int vsel = (((ln4 >> 3) & 1) << 2) | (((ln4 >> 2) & 1) << 1) | ((ln4 >> 1) & 1);
    bool wlane = ((lane & 1) == 0);

    __shared__ float yb[4][2][64];
    float h = 0.f;

#define LOADC(T, Dq0,Dq1,Uq0,Uq1,Bq0,Bq1,Cq0,Cq1)                              \
    {   int _t = (T);                                                          \
        Dq0 = *(const float4*)(dp + _t); Dq1 = *(const float4*)(dp + _t + 4);  \
        Bq0 = *(const float4*)(Bp + _t); Bq1 = *(const float4*)(Bp + _t + 4);  \
        Cq0 = *(const float4*)(Cp + _t); Cq1 = *(const float4*)(Cp + _t + 4);  \
        if (!rev) { Uq0 = *(const float4*)(up + _t); Uq1 = *(const float4*)(up + _t + 4); } \
        else {                                                                 \
            float4 p0 = *(const float4*)(up + (LL - 8 - _t));                  \
            float4 p1 = *(const float4*)(up + (LL - 4 - _t));                  \
            Uq0.x = p1.w; Uq0.y = p1.z; Uq0.z = p1.y; Uq0.w = p1.x;            \
            Uq1.x = p0.w; Uq1.y = p0.z; Uq1.z = p0.y; Uq1.w = p0.x; } }

    float4 D0,D1,U0,U1,Bq0,Bq1,Cq0,Cq1;
    LOADC(0, D0,D1,U0,U1,Bq0,Bq1,Cq0,Cq1)

    for (int t0 = 0; t0 < LL; t0 += 8) {
        float4 nD0,nD1,nU0,nU1,nB0,nB1,nC0,nC1;
        nD0=D0; nD1=D1; nU0=U0; nU1=U1; nB0=Bq0; nB1=Bq1; nC0=Cq0; nC1=Cq1;
        if (t0 + 8 < LL) LOADC(t0 + 8, nD0,nD1,nU0,nU1,nB0,nB1,nC0,nC1)

        float dl[8] = {D0.x,D0.y,D0.z,D0.w,D1.x,D1.y,D1.z,D1.w};
        float uu[8] = {U0.x,U0.y,U0.z,U0.w,U1.x,U1.y,U1.z,U1.w};
        float bb[8] = {Bq0.x,Bq0.y,Bq0.z,Bq0.w,Bq1.x,Bq1.y,Bq1.z,Bq1.w};
        float cc[8] = {Cq0.x,Cq0.y,Cq0.z,Cq0.w,Cq1.x,Cq1.y,Cq1.z,Cq1.w};
        float ee[8], gg[8], p[8];
        #pragma unroll
        for (int i = 0; i < 8; i++) ee[i] = ex2f(dl[i] * aa);
        #pragma unroll
        for (int i = 0; i < 8; i++) gg[i] = (dl[i] * uu[i]) * bb[i];
        #pragma unroll
        for (int i = 0; i < 8; i++) {
            h = fmaf(h, ee[i], gg[i]);
            p[i] = fmaf(Dv16, uu[i], h * cc[i]);
        }
        // distributed tree reduce over 16 lanes x 8 values
        #pragma unroll
        for (int i = 0; i < 8; i++) p[i] += __shfl_xor_sync(0xffffffffu, p[i], 8);
        float q0 = (lane & 8) ? p[4] : p[0];
        float q1 = (lane & 8) ? p[5] : p[1];
        float q2 = (lane & 8) ? p[6] : p[2];
        float q3 = (lane & 8) ? p[7] : p[3];
        q0 += __shfl_xor_sync(0xffffffffu, q0, 4);
        q1 += __shfl_xor_sync(0xffffffffu, q1, 4);
        q2 += __shfl_xor_sync(0xffffffffu, q2, 4);
        q3 += __shfl_xor_sync(0xffffffffu, q3, 4);
        float r0 = (lane & 4) ? q2 : q0;
        float r1 = (lane & 4) ? q3 : q1;
        r0 += __shfl_xor_sync(0xffffffffu, r0, 2);
        r1 += __shfl_xor_sync(0xffffffffu, r1, 2);
        float s = (lane & 2) ? r1 : r0;
        s += __shfl_xor_sync(0xffffffffu, s, 1);
        if (wlane) yb[warp][half][(t0 & 63) + vsel] = s;

        if ((t0 & 63) == 56) {
            __syncwarp();
            int idx = lane * 4, hs = idx >> 6, off = idx & 63;
            float4 v = *(float4*)&yb[warp][hs][off];
            *(float4*)(g_ys + ((size_t)bk * DI + dg * 8 + warp * 2 + hs) * LL + (t0 - 56) + off) = v;
            __syncwarp();
        }
        D0=nD0; D1=nD1; U0=nU0; U1=nU1; Bq0=nB0; Bq1=nB1; Cq0=nC0; Cq1=nC1;
    }
#undef LOADC
}

// ================= K5: combine the four direction outputs =================
__global__ void k5_combine()
{
    int hc = blockIdx.x % 6;
    int dc = (blockIdx.x / 6) & 15;
    int b  = blockIdx.x / 96;
    int d0 = dc * 16, h0 = hc * 8;
    __shared__ float s[16][392];
    int tid = threadIdx.x;
    const float* y0 = g_ys + ((size_t)(b * 4 + 0) * DI + d0) * LL;
    const float* y1 = g_ys + ((size_t)(b * 4 + 1) * DI + d0) * LL;
    const float* y2 = g_ys + ((size_t)(b * 4 + 2) * DI + d0) * LL;
    const float* y3 = g_ys + ((size_t)(b * 4 + 3) * DI + d0) * LL;
    int base = h0 * Ww;

    for (int idx = tid; idx < 16 * 384; idx += 256) {
        int d = idx / 384, p = idx % 384;
        int l = base + p;
        s[d][p] = y0[(size_t)d * LL + l] + y2[(size_t)d * LL + (LL - 1 - l)];
    }
    __syncthreads();
    for (int idx = tid; idx < 16 * 384; idx += 256) {
        int d = idx / 384, p = idx % 384;
        int w = p >> 3, hh = p & 7;
        int t1 = w * Hh + h0 + hh;
        float v = y1[(size_t)d * LL + t1] + y3[(size_t)d * LL + (LL - 1 - t1)];
        s[d][hh * Ww + w] += v;
    }
    __syncthreads();
    for (int idx = tid; idx < 384 * 16; idx += 256) {
        int p = idx >> 4, d = idx & 15;
        g_ycomb[((size_t)(b * LL + base + p)) * DI + d0 + d] = s[d][p];
    }
}

// ================= K6: LayerNorm(DI) + SiLU(z) gate =================
__global__ void k6_lngate(const float* __restrict__ og, const float* __restrict__ ob)
{
    int m = blockIdx.x;
    int tid = threadIdx.x;
    float v = g_ycomb[(size_t)m * DI + tid];
    float sm = v, sq = v * v;
    #pragma unroll
    for (int o = 16; o; o >>= 1) {
        sm += __shfl_xor_sync(0xffffffffu, sm, o);
        sq += __shfl_xor_sync(0xffffffffu, sq, o);
    }
    __shared__ float rs1[8], rs2[8];
    int w = tid >> 5, ln = tid & 31;
    if (ln == 0) { rs1[w] = sm; rs2[w] = sq; }
    __syncthreads();
    float ts = 0.f, tq = 0.f;
    #pragma unroll
    for (int i = 0; i < 8; i++) { ts += rs1[i]; tq += rs2[i]; }
    float mean = ts * (1.f / DI);
    float var  = tq * (1.f / DI) - mean * mean;
    float rstd = rsqrtf(var + 1e-5f);
    float zv = g_xz[(size_t)m * 512 + DI + tid];
    float gate = zv * sigmf(zv);
    g_yact[(size_t)m * DI + tid] = ((v - mean) * rstd * og[tid] + ob[tid]) * gate;
}

// ================= K7: out = x + (yact @ out_proj_w^T), (B,C,L) layout, 64x128 tile =================
__global__ void __launch_bounds__(256) k7_out(const float* __restrict__ Wout,
                                              const float* __restrict__ x,
                                              float* __restrict__ out)
{
    int b  = blockIdx.z;
    int c0 = blockIdx.x * 64;
    int l0 = blockIdx.y * 128;
    __shared__ float As[16][64];
    __shared__ float Bs[16][128];
    int tid = threadIdx.x;
    int tm = tid & 15, tn = tid >> 4;
    int arow = tid >> 2, akq = (tid & 3) * 4;
    int brow = tid >> 1, bkq = (tid & 1) * 8;
    float acc[4][8];
    #pragma unroll
    for (int i = 0; i < 4; i++)
        #pragma unroll
        for (int j = 0; j < 8; j++) acc[i][j] = 0.f;

    const float* Y = g_yact + (size_t)b * LL * DI;
    for (int k0 = 0; k0 < DI; k0 += 16) {
        float4 a0 = *(const float4*)(Wout + (size_t)(c0 + arow) * DI + k0 + akq);
        float4 b0 = *(const float4*)(Y + (size_t)(l0 + brow) * DI + k0 + bkq);
        float4 b1 = *(const float4*)(Y + (size_t)(l0 + brow) * DI + k0 + bkq + 4);
        __syncthreads();
        As[akq+0][arow]=a0.x; As[akq+1][arow]=a0.y; As[akq+2][arow]=a0.z; As[akq+3][arow]=a0.w;
        Bs[bkq+0][brow]=b0.x; Bs[bkq+1][brow]=b0.y; Bs[bkq+2][brow]=b0.z; Bs[bkq+3][brow]=b0.w;
        Bs[bkq+4][brow]=b1.x; Bs[bkq+5][brow]=b1.y; Bs[bkq+6][brow]=b1.z; Bs[bkq+7][brow]=b1.w;
        __syncthreads();
        #pragma unroll
        for (int kk = 0; kk < 16; kk++) {
            float4 av  = *(const float4*)&As[kk][tm << 2];
            float4 bv0 = *(const float4*)&Bs[kk][tn << 3];
            float4 bv1 = *(const float4*)&Bs[kk][(tn << 3) + 4];
            float am[4] = {av.x, av.y, av.z, av.w};
            float bn[8] = {bv0.x,bv0.y,bv0.z,bv0.w,bv1.x,bv1.y,bv1.z,bv1.w};
            #pragma unroll
            for (int i = 0; i < 4; i++)
                #pragma unroll
                for (int j = 0; j < 8; j++)
                    acc[i][j] = fmaf(am[i], bn[j], acc[i][j]);
        }
    }
    #pragma unroll
    for (int i = 0; i < 4; i++) {
        int c = c0 + (tm << 2) + i;
        size_t off = ((size_t)b * Cc + c) * LL + l0 + (tn << 3);
        float4 x0 = *(const float4*)(x + off);
        float4 x1 = *(const float4*)(x + off + 4);
        *(float4*)(out + off)     = make_float4(acc[i][0]+x0.x, acc[i][1]+x0.y, acc[i][2]+x0.z, acc[i][3]+x0.w);
        *(float4*)(out + off + 4) = make_float4(acc[i][4]+x1.x, acc[i][5]+x1.y, acc[i][6]+x1.z, acc[i][7]+x1.w);
    }
}

extern "C" void kernel_launch(void* const* d_in, const int* in_sizes, int n_in,
                              void* d_out, int out_size)
{
    const float* x          = (const float*)d_in[0];
    const float* ln1_g      = (const float*)d_in[1];
    const float* ln1_b      = (const float*)d_in[2];
    const float* in_proj_w  = (const float*)d_in[3];
    const float* conv_w     = (const float*)d_in[4];
    const float* conv_b     = (const float*)d_in[5];
    const float* x_proj_w   = (const float*)d_in[6];
    const float* dt_w       = (const float*)d_in[7];
    const float* dt_b       = (const float*)d_in[8];
    const float* A_logs     = (const float*)d_in[9];
    const float* Ds         = (const float*)d_in[10];
    const float* outn_g     = (const float*)d_in[11];
    const float* outn_b     = (const float*)d_in[12];
    const float* out_proj_w = (const float*)d_in[13];
    float* out = (float*)d_out;

    k0_ln<<<Bb * Hh, 256>>>(x, ln1_g, ln1_b);
    { dim3 g(BL / 128, 512 / 128); k1_gemm<<<g, 256>>>(in_proj_w); }
    k2_conv<<<Bb * 6 * 16, 256>>>(conv_w, conv_b);
    k3_xproj<<<Bb * Kk * 18, 256>>>(x_proj_w, dt_w, dt_b);
    k4_scan<<<32 * 16, 128>>>(A_logs, Ds);
    k5_combine<<<Bb * 16 * 6, 256>>>();
    k6_lngate<<<BL, 256>>>(outn_g, outn_b);
    { dim3 g(2, 18, Bb); k7_out<<<g, 256>>>(out_proj_w, x, out); }
}